// round 15
// baseline (speedup 1.0000x reference)
#include <cuda_runtime.h>
#include <cuda_bf16.h>
#include <cuda_fp8.h>
#include <cstdint>

// Problem constants (fixed by setup_inputs)
#define NE   8
#define DOUT 2048
#define DIN  2048
#define SEQ  8192
#define GRP  128
#define KBLK (DIN / GRP)    // 16 K-blocks
#define NBLK (DOUT / GRP)   // 16 N-blocks

// Scratch: quantized values stored as raw e4m3 bytes + fp32 scales.
__device__ __align__(16) uint8_t g_xq[SEQ * DIN];              // 16 MB
__device__ __align__(16) float   g_xs[SEQ * KBLK];             // 512 KB
__device__ __align__(16) uint8_t g_wq[NE * DOUT * DIN];        // 32 MB
__device__ __align__(16) float   g_ws[NE * NBLK * KBLK];       // 8 KB
// Progress counters: x per 128-row m-block (64 needed), w per (e,nb) strip (16 needed)
__device__ int g_xcnt[64];
__device__ int g_wcnt[NE * NBLK];

__global__ void clear_cnt_kernel() {
    if (threadIdx.x < 64) g_xcnt[threadIdx.x] = 0;
    if (threadIdx.x < NE * NBLK) g_wcnt[threadIdx.x] = 0;
}

__device__ __forceinline__ int ld_acquire(const int* p) {
    int v;
    asm volatile("ld.acquire.gpu.global.b32 %0, [%1];" : "=r"(v) : "l"(p) : "memory");
    return v;
}

// fp8 e4m3 quantize: clip+RN == RN-satfinite convert of v/scale
__device__ __forceinline__ uint32_t quant4_e4m3(float4 v, float scale) {
    float4 c = make_float4(v.x / scale, v.y / scale, v.z / scale, v.w / scale);
    __nv_fp8x4_e4m3 q(c);   // RN, satfinite (== clip to +-448 then RN)
    return *reinterpret_cast<uint32_t*>(&q);
}

// ---------------------------------------------------------------------------
// Grid layout (single fused launch, blockIdx order = schedule order):
//   [0, 2048)            : w-quant CTAs (one 128x128 block each)
//   [2048, 2048+4096)    : x-quant CTAs (32 1x128 tiles = 2 rows each)
//   [6144, 6144+1024)    : gemm CTAs, flag-gated on their quant inputs
// ---------------------------------------------------------------------------
#define QW_CTAS 2048
#define QX_CTAS 4096
#define GEMM_CTAS 1024

#define BM    128
#define BN    128
#define BKS   128
#define STG   3
#define TILEB 16384               // 128 rows x 128 B
#define STAGEB (2 * TILEB)
#define SMEM_REQ (STG * STAGEB)   // 98304 B -> 2 CTAs/SM

__device__ __forceinline__ void cp16(uint32_t dst, const void* src, int src_bytes) {
    asm volatile("cp.async.cg.shared.global [%0], [%1], 16, %2;\n"
                 :: "r"(dst), "l"(src), "r"(src_bytes) : "memory");
}
__device__ __forceinline__ void ldm_x4(uint32_t r[4], uint32_t addr) {
    asm volatile("ldmatrix.sync.aligned.m8n8.x4.shared.b16 {%0,%1,%2,%3}, [%4];"
                 : "=r"(r[0]), "=r"(r[1]), "=r"(r[2]), "=r"(r[3]) : "r"(addr));
}
__device__ __forceinline__ void mma_fp8(float c[4], const uint32_t a[4], const uint32_t b[2]) {
    asm volatile(
        "mma.sync.aligned.m16n8k32.row.col.f32.e4m3.e4m3.f32 "
        "{%0,%1,%2,%3}, {%4,%5,%6,%7}, {%8,%9}, {%0,%1,%2,%3};"
        : "+f"(c[0]), "+f"(c[1]), "+f"(c[2]), "+f"(c[3])
        : "r"(a[0]), "r"(a[1]), "r"(a[2]), "r"(a[3]), "r"(b[0]), "r"(b[1]));
}
__device__ __forceinline__ uint32_t smem_u32(const void* p) {
    uint32_t a;
    asm("{ .reg .u64 t; cvta.to.shared.u64 t, %1; cvt.u32.u64 %0, t; }" : "=r"(a) : "l"(p));
    return a;
}
// SW128 swizzle, 16B-granular: physical = row*128 + (off16 ^ ((row&7)<<4))
__device__ __forceinline__ uint32_t swz(int row, int off) {
    return (uint32_t)(row * 128 + (off ^ ((row & 7) << 4)));
}

__global__ __launch_bounds__(256, 2) void fused_kernel(const float* __restrict__ x,
                                                       const float* __restrict__ w,
                                                       float* __restrict__ out,
                                                       const int* __restrict__ tpe) {
    extern __shared__ __align__(128) uint8_t sm[];
    const int tid  = threadIdx.x;
    const int lane = tid & 31;
    const int wrp  = tid >> 5;
    const int bid  = blockIdx.x;

    // =================== W-QUANT CTAs ===================
    if (bid < QW_CTAS) {
        int e   = bid >> 8;
        int rem = bid & 255;
        int nb  = rem >> 4;
        int kb  = rem & 15;

        const size_t base = ((size_t)(e * DOUT + nb * GRP)) * DIN + kb * GRP;
        const float* src = w + base;
        uint8_t* dst = g_wq + base;

        float a = 0.0f;
#pragma unroll
        for (int i = tid; i < 4096; i += 256) {
            int r = i >> 5, c = i & 31;
            float4 v = *reinterpret_cast<const float4*>(src + (size_t)r * DIN + c * 4);
            a = fmaxf(a, fmaxf(fmaxf(fabsf(v.x), fabsf(v.y)), fmaxf(fabsf(v.z), fabsf(v.w))));
        }
#pragma unroll
        for (int o = 16; o; o >>= 1) a = fmaxf(a, __shfl_xor_sync(0xffffffffu, a, o));

        __shared__ float red[8];
        __shared__ float s_scale;
        if (lane == 0) red[wrp] = a;
        __syncthreads();
        if (tid == 0) {
            float m = red[0];
#pragma unroll
            for (int i = 1; i < 8; i++) m = fmaxf(m, red[i]);
            s_scale = fmaxf(m, 1e-12f) / 448.0f;
        }
        __syncthreads();
        float scale = s_scale;

#pragma unroll
        for (int i = tid; i < 4096; i += 256) {
            int r = i >> 5, c = i & 31;
            float4 v = *reinterpret_cast<const float4*>(src + (size_t)r * DIN + c * 4);
            *reinterpret_cast<uint32_t*>(dst + (size_t)r * DIN + c * 4) = quant4_e4m3(v, scale);
        }
        if (tid == 0) g_ws[(e * NBLK + nb) * KBLK + kb] = scale;

        __syncthreads();
        __threadfence();
        if (tid == 0) atomicAdd(&g_wcnt[e * NBLK + nb], 1);
        return;
    }

    // =================== X-QUANT CTAs ===================
    if (bid < QW_CTAS + QX_CTAS) {
        int bx = bid - QW_CTAS;                 // 0..4095, covers rows [bx*2, bx*2+2)
        int t0 = (bx * 8 + wrp) * 4;

        float4 v[4];
        float  a[4];
#pragma unroll
        for (int j = 0; j < 4; j++) {
            v[j] = *reinterpret_cast<const float4*>(x + (size_t)(t0 + j) * GRP + lane * 4);
            a[j] = fmaxf(fmaxf(fabsf(v[j].x), fabsf(v[j].y)), fmaxf(fabsf(v[j].z), fabsf(v[j].w)));
        }
#pragma unroll
        for (int o = 16; o; o >>= 1)
#pragma unroll
            for (int j = 0; j < 4; j++)
                a[j] = fmaxf(a[j], __shfl_xor_sync(0xffffffffu, a[j], o));

#pragma unroll
        for (int j = 0; j < 4; j++) {
            float s = fmaxf(a[j], 1e-12f) / 448.0f;
            *reinterpret_cast<uint32_t*>(g_xq + (size_t)(t0 + j) * GRP + lane * 4) = quant4_e4m3(v[j], s);
            if (lane == 0) g_xs[t0 + j] = s;
        }

        __syncthreads();
        __threadfence();
        if (tid == 0) atomicAdd(&g_xcnt[bx >> 6], 1);
        return;
    }

    // =================== GEMM CTAs ===================
    const uint32_t s0 = smem_u32(sm);
    const int g  = bid - QW_CTAS - QX_CTAS;     // 0..1023
    const int my = g >> 4;                       // m-tile 0..63
    const int nx = g & 15;                       // n-tile 0..15
    const int m0 = my * BM;
    const int n0 = nx * BN;
    const int wm = wrp & 3;                      // 4 warps along M (32 rows)
    const int wn = wrp >> 2;                     // 2 warps along N (64 cols)

    // Expert lookup (prefix sum over 8 counts)
    int accv = 0, e = -1, rs = 0, re = 0;
#pragma unroll
    for (int i = 0; i < NE; i++) {
        int c = tpe[i];
        if (e < 0 && m0 >= accv && m0 < accv + c) { e = i; rs = accv; re = accv + c; }
        accv += c;
    }
    if (e < 0) { e = 0; rs = 0; re = 0; }       // fully zero tile

    // Wait for this tile's quant inputs (thread 0 spins, then CTA sync)
    if (tid == 0) {
        const int* xp = &g_xcnt[my];
        const int* wp = &g_wcnt[e * NBLK + nx];
        while (ld_acquire(xp) < 64) __nanosleep(128);
        while (ld_acquire(wp) < 16) __nanosleep(128);
    }
    __syncthreads();

    const uint8_t* Aptr = g_xq;
    const uint8_t* Bptr = g_wq + (size_t)e * DOUT * DIN;

    auto load_stage = [&](int kb, int st) {
        const int kc = kb * BKS;
        const uint32_t ab = s0 + st * STAGEB;
        const uint32_t bb = ab + TILEB;
#pragma unroll
        for (int i = 0; i < 4; i++) {
            int cid = tid + 256 * i;              // 0..1023
            int row = cid >> 3;
            int off = (cid & 7) * 16;
            uint32_t sw = swz(row, off);
            int gr = m0 + row;
            cp16(ab + sw, Aptr + (size_t)gr * DIN + kc + off,
                 (gr >= rs && gr < re) ? 16 : 0);
            cp16(bb + sw, Bptr + (size_t)(n0 + row) * DIN + kc + off, 16);
        }
        asm volatile("cp.async.commit_group;\n" ::: "memory");
    };

    auto ldA = [&](int st, int ks, uint32_t af[2][4]) {
        const int k0 = ks * 32;
#pragma unroll
        for (int mi = 0; mi < 2; mi++) {
            int row = wm * 32 + mi * 16 + (lane & 15);
            int cb  = k0 + ((lane >> 4) << 4);
            ldm_x4(af[mi], s0 + st * STAGEB + swz(row, cb));
        }
    };
    auto ldB = [&](int st, int ks, uint32_t bf[8][2]) {
        const int k0 = ks * 32;
#pragma unroll
        for (int nj = 0; nj < 4; nj++) {
            int gg = lane >> 3;
            int n  = wn * 64 + nj * 16 + ((gg >> 1) << 3) + (lane & 7);
            int kk = k0 + ((gg & 1) << 4);
            uint32_t r[4];
            ldm_x4(r, s0 + st * STAGEB + TILEB + swz(n, kk));
            bf[nj * 2 + 0][0] = r[0]; bf[nj * 2 + 0][1] = r[1];
            bf[nj * 2 + 1][0] = r[2]; bf[nj * 2 + 1][1] = r[3];
        }
    };

    float tot[2][8][4];
#pragma unroll
    for (int mi = 0; mi < 2; mi++)
#pragma unroll
        for (int ni = 0; ni < 8; ni++)
#pragma unroll
            for (int q = 0; q < 4; q++) tot[mi][ni][q] = 0.f;

    const int swbase = (e * NBLK + nx) * KBLK;
    const int ra0 = m0 + wm * 32 + (lane >> 2);
    float sold[2][2];   // running block scale per (mi, row-half)

    load_stage(0, 0);
    load_stage(1, 1);

#pragma unroll 1
    for (int kb = 0; kb < KBLK; kb++) {
        const int st = kb % STG;

        // Scales via L2 (lines may have been L1-cached stale by sibling CTAs)
        const float swv = __ldcg(&g_ws[swbase + kb]);
        float snew[2][2];
#pragma unroll
        for (int mi = 0; mi < 2; mi++) {
            snew[mi][0] = __ldcg(&g_xs[(ra0 + mi * 16) * KBLK + kb]) * swv;
            snew[mi][1] = __ldcg(&g_xs[(ra0 + mi * 16 + 8) * KBLK + kb]) * swv;
        }

        asm volatile("cp.async.wait_group 1;\n" ::: "memory");
        __syncthreads();   // stage kb visible; all warps done with stage kb-1

        if (kb + 2 < KBLK) load_stage(kb + 2, (kb + 2) % STG);
        else               asm volatile("cp.async.commit_group;\n" ::: "memory");

        // Rescale running accumulators into the new block-scale units
        if (kb) {
            float ratio[2][2];
#pragma unroll
            for (int mi = 0; mi < 2; mi++) {
                ratio[mi][0] = sold[mi][0] / snew[mi][0];
                ratio[mi][1] = sold[mi][1] / snew[mi][1];
            }
#pragma unroll
            for (int mi = 0; mi < 2; mi++)
#pragma unroll
                for (int ni = 0; ni < 8; ni++) {
                    tot[mi][ni][0] *= ratio[mi][0];
                    tot[mi][ni][1] *= ratio[mi][0];
                    tot[mi][ni][2] *= ratio[mi][1];
                    tot[mi][ni][3] *= ratio[mi][1];
                }
        }
#pragma unroll
        for (int mi = 0; mi < 2; mi++) { sold[mi][0] = snew[mi][0]; sold[mi][1] = snew[mi][1]; }

        // 4 k-steps; QMMAs accumulate directly into tot
#pragma unroll
        for (int ks = 0; ks < 4; ks++) {
            uint32_t af[2][4];
            uint32_t bf[8][2];
            ldA(st, ks, af);
            ldB(st, ks, bf);
#pragma unroll
            for (int mi = 0; mi < 2; mi++)
#pragma unroll
                for (int ni = 0; ni < 8; ni++)
                    mma_fp8(tot[mi][ni], af[mi], bf[ni]);
        }
    }

    // Epilogue: apply the final block scale; rows outside expert range -> zeros
#pragma unroll
    for (int mi = 0; mi < 2; mi++) {
        int r0 = m0 + wm * 32 + mi * 16 + (lane >> 2);
        int r1 = r0 + 8;
        bool in0 = (r0 >= rs && r0 < re);
        bool in1 = (r1 >= rs && r1 < re);
        float f0 = in0 ? sold[mi][0] : 0.f;
        float f1 = in1 ? sold[mi][1] : 0.f;
#pragma unroll
        for (int ni = 0; ni < 8; ni++) {
            int col = n0 + wn * 64 + ni * 8 + ((lane & 3) << 1);
            float2 v0 = {tot[mi][ni][0] * f0, tot[mi][ni][1] * f0};
            float2 v1 = {tot[mi][ni][2] * f1, tot[mi][ni][3] * f1};
            *reinterpret_cast<float2*>(out + (size_t)r0 * DOUT + col) = v0;
            *reinterpret_cast<float2*>(out + (size_t)r1 * DOUT + col) = v1;
        }
    }
}

// ---------------------------------------------------------------------------
extern "C" void kernel_launch(void* const* d_in, const int* in_sizes, int n_in,
                              void* d_out, int out_size) {
    const float* x   = (const float*)d_in[0];
    const float* w   = (const float*)d_in[1];
    const int*   tpe = (const int*)d_in[2];
    float* out = (float*)d_out;

    cudaFuncSetAttribute(fused_kernel, cudaFuncAttributeMaxDynamicSharedMemorySize, SMEM_REQ);

    clear_cnt_kernel<<<1, 256>>>();
    fused_kernel<<<QW_CTAS + QX_CTAS + GEMM_CTAS, 256, SMEM_REQ>>>(x, w, out, tpe);
}

// round 16
// speedup vs baseline: 1.2124x; 1.2124x over previous
#include <cuda_runtime.h>
#include <cuda_bf16.h>
#include <cuda_fp8.h>
#include <cstdint>

// Problem constants (fixed by setup_inputs)
#define NE   8
#define DOUT 2048
#define DIN  2048
#define SEQ  8192
#define GRP  128
#define KBLK (DIN / GRP)    // 16 K-blocks
#define NBLK (DOUT / GRP)   // 16 N-blocks

// Scratch: quantized values stored as raw e4m3 bytes + fp32 scales.
__device__ __align__(16) uint8_t g_xq[SEQ * DIN];              // 16 MB
__device__ __align__(16) float   g_xs[SEQ * KBLK];             // 512 KB
__device__ __align__(16) uint8_t g_wq[NE * DOUT * DIN];        // 32 MB
__device__ __align__(16) float   g_ws[NE * NBLK * KBLK];       // 8 KB

// fp8 e4m3 quantize: clip+RN == RN-satfinite convert of v/scale
__device__ __forceinline__ uint32_t quant4_e4m3(float4 v, float scale) {
    float4 c = make_float4(v.x / scale, v.y / scale, v.z / scale, v.w / scale);
    __nv_fp8x4_e4m3 q(c);   // RN, satfinite (== clip to +-448 then RN)
    return *reinterpret_cast<uint32_t*>(&q);
}

// ---------------------------------------------------------------------------
// Fused quant kernel (R12/R14 configuration — best measured, ~48us).
// Blocks [0,2048): per-128x128 weight block, two-pass (pass 2 is L2-hot).
// Blocks [2048,...): activation 1x128 tiles, 4 per warp.
// ---------------------------------------------------------------------------
#define QW_BLOCKS (NE * NBLK * KBLK)          // 2048
#define QX_BLOCKS (SEQ * KBLK / 32)           // 4096

__global__ __launch_bounds__(256) void quant_all_kernel(const float* __restrict__ x,
                                                        const float* __restrict__ w) {
    if (blockIdx.x < QW_BLOCKS) {
        int b   = blockIdx.x;
        int e   = b >> 8;
        int rem = b & 255;
        int nb  = rem >> 4;
        int kb  = rem & 15;

        const size_t base = ((size_t)(e * DOUT + nb * GRP)) * DIN + kb * GRP;
        const float* src = w + base;
        uint8_t* dst = g_wq + base;

        int tid  = threadIdx.x;
        int lane = tid & 31;
        int warp = tid >> 5;

        float a = 0.0f;
#pragma unroll
        for (int i = tid; i < 4096; i += 256) {
            int r = i >> 5, c = i & 31;
            float4 v = *reinterpret_cast<const float4*>(src + (size_t)r * DIN + c * 4);
            a = fmaxf(a, fmaxf(fmaxf(fabsf(v.x), fabsf(v.y)), fmaxf(fabsf(v.z), fabsf(v.w))));
        }
#pragma unroll
        for (int o = 16; o; o >>= 1) a = fmaxf(a, __shfl_xor_sync(0xffffffffu, a, o));

        __shared__ float red[8];
        __shared__ float s_scale;
        if (lane == 0) red[warp] = a;
        __syncthreads();
        if (tid == 0) {
            float m = red[0];
#pragma unroll
            for (int i = 1; i < 8; i++) m = fmaxf(m, red[i]);
            s_scale = fmaxf(m, 1e-12f) / 448.0f;
        }
        __syncthreads();
        float scale = s_scale;

#pragma unroll
        for (int i = tid; i < 4096; i += 256) {
            int r = i >> 5, c = i & 31;
            float4 v = *reinterpret_cast<const float4*>(src + (size_t)r * DIN + c * 4);
            *reinterpret_cast<uint32_t*>(dst + (size_t)r * DIN + c * 4) = quant4_e4m3(v, scale);
        }
        if (tid == 0) g_ws[(e * NBLK + nb) * KBLK + kb] = scale;
    } else {
        int bx   = blockIdx.x - QW_BLOCKS;
        int warp = threadIdx.x >> 5;
        int lane = threadIdx.x & 31;
        int t0 = (bx * 8 + warp) * 4;

        float4 v[4];
        float  a[4];
#pragma unroll
        for (int j = 0; j < 4; j++) {
            v[j] = *reinterpret_cast<const float4*>(x + (size_t)(t0 + j) * GRP + lane * 4);
            a[j] = fmaxf(fmaxf(fabsf(v[j].x), fabsf(v[j].y)), fmaxf(fabsf(v[j].z), fabsf(v[j].w)));
        }
#pragma unroll
        for (int o = 16; o; o >>= 1)
#pragma unroll
            for (int j = 0; j < 4; j++)
                a[j] = fmaxf(a[j], __shfl_xor_sync(0xffffffffu, a[j], o));

#pragma unroll
        for (int j = 0; j < 4; j++) {
            float s = fmaxf(a[j], 1e-12f) / 448.0f;
            *reinterpret_cast<uint32_t*>(g_xq + (size_t)(t0 + j) * GRP + lane * 4) = quant4_e4m3(v[j], s);
            if (lane == 0) g_xs[t0 + j] = s;
        }
    }
}

// ---------------------------------------------------------------------------
// GEMM: 128x64 CTA tile, 128 threads / 4 warps (each the proven 32x64 warp
// tile), BK=128 stages, fp8 QMMA, SW128 swizzle, 3-stage cp.async.
// 72KB smem + 128 regs -> 3 CTAs/SM (444 workers, 4.6 waves -> 92% tail util
// vs 86.5% at BN=128). Running block-scale rescale, in-place accumulation.
// ---------------------------------------------------------------------------
#define BM    128
#define BN    64
#define BKS   128
#define STG   3
#define ATILEB 16384              // 128 rows x 128 B
#define BTILEB 8192               // 64 rows x 128 B
#define STAGEB (ATILEB + BTILEB)  // 24 KB
#define SMEM_REQ (STG * STAGEB)   // 73728 B -> 3 CTAs/SM
#define NT    128

__device__ __forceinline__ void cp16(uint32_t dst, const void* src, int src_bytes) {
    asm volatile("cp.async.cg.shared.global [%0], [%1], 16, %2;\n"
                 :: "r"(dst), "l"(src), "r"(src_bytes) : "memory");
}
__device__ __forceinline__ void ldm_x4(uint32_t r[4], uint32_t addr) {
    asm volatile("ldmatrix.sync.aligned.m8n8.x4.shared.b16 {%0,%1,%2,%3}, [%4];"
                 : "=r"(r[0]), "=r"(r[1]), "=r"(r[2]), "=r"(r[3]) : "r"(addr));
}
__device__ __forceinline__ void mma_fp8(float c[4], const uint32_t a[4], const uint32_t b[2]) {
    asm volatile(
        "mma.sync.aligned.m16n8k32.row.col.f32.e4m3.e4m3.f32 "
        "{%0,%1,%2,%3}, {%4,%5,%6,%7}, {%8,%9}, {%0,%1,%2,%3};"
        : "+f"(c[0]), "+f"(c[1]), "+f"(c[2]), "+f"(c[3])
        : "r"(a[0]), "r"(a[1]), "r"(a[2]), "r"(a[3]), "r"(b[0]), "r"(b[1]));
}
__device__ __forceinline__ uint32_t smem_u32(const void* p) {
    uint32_t a;
    asm("{ .reg .u64 t; cvta.to.shared.u64 t, %1; cvt.u32.u64 %0, t; }" : "=r"(a) : "l"(p));
    return a;
}
// SW128 swizzle, 16B-granular: physical = row*128 + (off16 ^ ((row&7)<<4))
__device__ __forceinline__ uint32_t swz(int row, int off) {
    return (uint32_t)(row * 128 + (off ^ ((row & 7) << 4)));
}

__global__ __launch_bounds__(NT, 3) void gemm_kernel(float* __restrict__ out,
                                                     const int* __restrict__ tpe) {
    extern __shared__ __align__(128) uint8_t sm[];
    const uint32_t s0 = smem_u32(sm);

    const int tid  = threadIdx.x;
    const int lane = tid & 31;
    const int wm   = tid >> 5;          // 4 warps along M (32 rows each), wn = 0

    const int m0 = blockIdx.y * BM;
    const int n0 = blockIdx.x * BN;

    // Expert lookup (prefix sum over 8 counts)
    int accv = 0, e = -1, rs = 0, re = 0;
#pragma unroll
    for (int i = 0; i < NE; i++) {
        int c = tpe[i];
        if (e < 0 && m0 >= accv && m0 < accv + c) { e = i; rs = accv; re = accv + c; }
        accv += c;
    }
    if (e < 0) { e = 0; rs = 0; re = 0; }   // fully zero tile

    const uint8_t* Aptr = g_xq;
    const uint8_t* Bptr = g_wq + (size_t)e * DOUT * DIN;

    // Stage loader: 1024 A chunks + 512 B chunks of 16B; 12 per thread.
    auto load_stage = [&](int kb, int st) {
        const int kc = kb * BKS;
        const uint32_t ab = s0 + st * STAGEB;
        const uint32_t bb = ab + ATILEB;
#pragma unroll
        for (int i = 0; i < 8; i++) {               // A: 128 rows x 8 chunks
            int cid = tid + NT * i;
            int row = cid >> 3;
            int off = (cid & 7) * 16;
            int gr = m0 + row;
            cp16(ab + swz(row, off), Aptr + (size_t)gr * DIN + kc + off,
                 (gr >= rs && gr < re) ? 16 : 0);
        }
#pragma unroll
        for (int i = 0; i < 4; i++) {               // B: 64 rows x 8 chunks
            int cid = tid + NT * i;
            int row = cid >> 3;
            int off = (cid & 7) * 16;
            cp16(bb + swz(row, off), Bptr + (size_t)(n0 + row) * DIN + kc + off, 16);
        }
        asm volatile("cp.async.commit_group;\n" ::: "memory");
    };

    // Fragment loaders (verified R9 lane mapping, wn fixed at 0)
    auto ldA = [&](int st, int ks, uint32_t af[2][4]) {
        const int k0 = ks * 32;
#pragma unroll
        for (int mi = 0; mi < 2; mi++) {
            int row = wm * 32 + mi * 16 + (lane & 15);
            int cb  = k0 + ((lane >> 4) << 4);
            ldm_x4(af[mi], s0 + st * STAGEB + swz(row, cb));
        }
    };
    auto ldB = [&](int st, int ks, uint32_t bf[8][2]) {
        const int k0 = ks * 32;
#pragma unroll
        for (int nj = 0; nj < 4; nj++) {
            int g  = lane >> 3;
            int n  = nj * 16 + ((g >> 1) << 3) + (lane & 7);
            int kk = k0 + ((g & 1) << 4);
            uint32_t r[4];
            ldm_x4(r, s0 + st * STAGEB + ATILEB + swz(n, kk));
            bf[nj * 2 + 0][0] = r[0]; bf[nj * 2 + 0][1] = r[1];
            bf[nj * 2 + 1][0] = r[2]; bf[nj * 2 + 1][1] = r[3];
        }
    };

    float tot[2][8][4];
#pragma unroll
    for (int mi = 0; mi < 2; mi++)
#pragma unroll
        for (int ni = 0; ni < 8; ni++)
#pragma unroll
            for (int q = 0; q < 4; q++) tot[mi][ni][q] = 0.f;

    const int swbase = (e * NBLK + (n0 >> 7)) * KBLK;
    const int ra0 = m0 + wm * 32 + (lane >> 2);
    float sold[2][2];   // running block scale per (mi, row-half)

    load_stage(0, 0);
    load_stage(1, 1);

#pragma unroll 1
    for (int kb = 0; kb < KBLK; kb++) {
        const int st = kb % STG;

        // Prefetch this K-block's scales (independent of smem state)
        const float swv = g_ws[swbase + kb];
        float snew[2][2];
#pragma unroll
        for (int mi = 0; mi < 2; mi++) {
            snew[mi][0] = g_xs[(ra0 + mi * 16) * KBLK + kb] * swv;
            snew[mi][1] = g_xs[(ra0 + mi * 16 + 8) * KBLK + kb] * swv;
        }

        asm volatile("cp.async.wait_group 1;\n" ::: "memory");
        __syncthreads();   // stage kb visible; all warps done with stage kb-1

        if (kb + 2 < KBLK) load_stage(kb + 2, (kb + 2) % STG);
        else               asm volatile("cp.async.commit_group;\n" ::: "memory");

        // Rescale running accumulators into the new block-scale units
        if (kb) {
            float ratio[2][2];
#pragma unroll
            for (int mi = 0; mi < 2; mi++) {
                ratio[mi][0] = sold[mi][0] / snew[mi][0];
                ratio[mi][1] = sold[mi][1] / snew[mi][1];
            }
#pragma unroll
            for (int mi = 0; mi < 2; mi++)
#pragma unroll
                for (int ni = 0; ni < 8; ni++) {
                    tot[mi][ni][0] *= ratio[mi][0];
                    tot[mi][ni][1] *= ratio[mi][0];
                    tot[mi][ni][2] *= ratio[mi][1];
                    tot[mi][ni][3] *= ratio[mi][1];
                }
        }
#pragma unroll
        for (int mi = 0; mi < 2; mi++) { sold[mi][0] = snew[mi][0]; sold[mi][1] = snew[mi][1]; }

        // 4 k-steps; QMMAs accumulate directly into tot
#pragma unroll
        for (int ks = 0; ks < 4; ks++) {
            uint32_t af[2][4];
            uint32_t bf[8][2];
            ldA(st, ks, af);
            ldB(st, ks, bf);
#pragma unroll
            for (int mi = 0; mi < 2; mi++)
#pragma unroll
                for (int ni = 0; ni < 8; ni++)
                    mma_fp8(tot[mi][ni], af[mi], bf[ni]);
        }
    }

    // Epilogue: apply the final block scale; rows outside expert range -> zeros
#pragma unroll
    for (int mi = 0; mi < 2; mi++) {
        int r0 = m0 + wm * 32 + mi * 16 + (lane >> 2);
        int r1 = r0 + 8;
        bool in0 = (r0 >= rs && r0 < re);
        bool in1 = (r1 >= rs && r1 < re);
        float f0 = in0 ? sold[mi][0] : 0.f;
        float f1 = in1 ? sold[mi][1] : 0.f;
#pragma unroll
        for (int ni = 0; ni < 8; ni++) {
            int col = n0 + ni * 8 + ((lane & 3) << 1);
            float2 v0 = {tot[mi][ni][0] * f0, tot[mi][ni][1] * f0};
            float2 v1 = {tot[mi][ni][2] * f1, tot[mi][ni][3] * f1};
            *reinterpret_cast<float2*>(out + (size_t)r0 * DOUT + col) = v0;
            *reinterpret_cast<float2*>(out + (size_t)r1 * DOUT + col) = v1;
        }
    }
}

// ---------------------------------------------------------------------------
extern "C" void kernel_launch(void* const* d_in, const int* in_sizes, int n_in,
                              void* d_out, int out_size) {
    const float* x   = (const float*)d_in[0];
    const float* w   = (const float*)d_in[1];
    const int*   tpe = (const int*)d_in[2];
    float* out = (float*)d_out;

    cudaFuncSetAttribute(gemm_kernel, cudaFuncAttributeMaxDynamicSharedMemorySize, SMEM_REQ);

    quant_all_kernel<<<QW_BLOCKS + QX_BLOCKS, 256>>>(x, w);
    gemm_kernel<<<dim3(DOUT / BN, SEQ / BM), NT, SMEM_REQ>>>(out, tpe);
}